// round 5
// baseline (speedup 1.0000x reference)
#include <cuda_runtime.h>

#define BB 128
#define PP 34125
#define OO 16
#define CC 21
#define NEGPOS 3
#define VAR0 0.1f
#define VAR1 0.2f
#define THRESH 0.35f
#define NT 512
#define NW (NT/32)

// scratch (device globals: no allocation allowed)
__device__ float    g_bto[BB*PP];
__device__ int      g_bti[BB*PP];
__device__ unsigned g_mined[BB*PP];
__device__ float    g_ll[BB];
__device__ float    g_lc[BB];
__device__ int      g_np[BB];

__device__ __forceinline__ float warp_red_f(float v) {
    #pragma unroll
    for (int o = 16; o; o >>= 1) v += __shfl_down_sync(0xffffffffu, v, o);
    return v;
}
__device__ __forceinline__ int warp_red_i(int v) {
    #pragma unroll
    for (int o = 16; o; o >>= 1) v += __shfl_down_sync(0xffffffffu, v, o);
    return v;
}
__device__ __forceinline__ float sl1(float d) {
    float ad = fabsf(d);
    return (ad < 1.0f) ? 0.5f * d * d : ad - 0.5f;
}

__global__ __launch_bounds__(NT) void mb_main(
    const float4* __restrict__ loc4,     // [B,P] float4
    const float*  __restrict__ conf,     // [B,P,C]
    const float4* __restrict__ priors4,  // [P] float4 (cx,cy,w,h)
    const float*  __restrict__ targets)  // [B,O,5]
{
    const int b = blockIdx.x;
    const int tid = threadIdx.x;
    const int lane = tid & 31;
    const int wid = tid >> 5;

    __shared__ float s_t[OO][5];
    __shared__ float s_area[OO];
    __shared__ unsigned long long s_bpk[OO];
    __shared__ float s_conf[NW][32 * CC];
    __shared__ unsigned s_hist[256];
    __shared__ float s_rll[NW], s_rcep[NW];
    __shared__ int   s_rnp[NW];
    __shared__ float s_llT, s_cepT, s_negT;
    __shared__ int   s_npT;
    __shared__ unsigned sh_pref, sh_pmask;
    __shared__ int sh_kk;

    // load truths + init
    if (tid < OO * 5) s_t[tid / 5][tid % 5] = targets[b * OO * 5 + tid];
    if (tid < OO) s_bpk[tid] = 0ULL;
    __syncthreads();
    if (tid < OO) {
        s_area[tid] = (s_t[tid][2] - s_t[tid][0]) * (s_t[tid][3] - s_t[tid][1]);
    }
    __syncthreads();

    // ---- Phase 1: matching ----
    unsigned long long bpk[OO];
    #pragma unroll
    for (int o = 0; o < OO; o++) bpk[o] = 0ULL;

    for (int p = tid; p < PP; p += NT) {
        float4 pr = priors4[p];
        float px0 = pr.x - pr.z * 0.5f, py0 = pr.y - pr.w * 0.5f;
        float px1 = pr.x + pr.z * 0.5f, py1 = pr.y + pr.w * 0.5f;
        float pa = (px1 - px0) * (py1 - py0);
        float bto = -1.0f; int bti = 0;
        #pragma unroll
        for (int o = 0; o < OO; o++) {
            float ix0 = fmaxf(s_t[o][0], px0);
            float iy0 = fmaxf(s_t[o][1], py0);
            float ix1 = fminf(s_t[o][2], px1);
            float iy1 = fminf(s_t[o][3], py1);
            float iw = fmaxf(ix1 - ix0, 0.0f);
            float ih = fmaxf(iy1 - iy0, 0.0f);
            float inter = iw * ih;
            float iou = __fdividef(inter, s_area[o] + pa - inter);
            if (iou > bto) { bto = iou; bti = o; }
            unsigned long long key =
                ((unsigned long long)__float_as_uint(iou) << 32) |
                (unsigned long long)(0xFFFFFFFFu - (unsigned)p);
            if (key > bpk[o]) bpk[o] = key;
        }
        g_bto[b * PP + p] = bto;
        g_bti[b * PP + p] = bti;
    }
    #pragma unroll
    for (int o = 0; o < OO; o++) atomicMax(&s_bpk[o], bpk[o]);
    __syncthreads();

    if (tid == 0) {
        // sequential overrides, last-wins
        for (int o = 0; o < OO; o++) {
            unsigned pstar = 0xFFFFFFFFu - (unsigned)(s_bpk[o] & 0xFFFFFFFFULL);
            g_bto[b * PP + pstar] = 2.0f;
            g_bti[b * PP + pstar] = o;
        }
    }
    __syncthreads();

    // ---- Phase 2: CE + loc loss (warp-staged conf transpose) ----
    float ll = 0.0f, cep = 0.0f; int np = 0;
    for (int p32 = wid * 32; p32 < PP; p32 += NW * 32) {
        int n = min(32, PP - p32);
        const float* cbase = conf + ((size_t)b * PP + p32) * CC;
        float* sc = s_conf[wid];
        for (int i = lane; i < n * CC; i += 32) sc[i] = cbase[i];
        __syncwarp();
        if (lane < n) {
            int p = p32 + lane;
            const float* row = sc + lane * CC;   // stride 21: conflict-free
            float mx = row[0];
            #pragma unroll
            for (int c = 1; c < CC; c++) mx = fmaxf(mx, row[c]);
            float s = 0.0f;
            #pragma unroll
            for (int c = 0; c < CC; c++) s += __expf(row[c] - mx);
            float lse = mx + __logf(s);

            float bto = g_bto[b * PP + p];
            int   bti = g_bti[b * PP + p];
            int ct = (bto < THRESH) ? 0 : (int)s_t[bti][4];
            float ce = lse - row[ct];
            bool pos = ct > 0;
            g_mined[b * PP + p] = pos ? 0u : __float_as_uint(ce);
            if (pos) {
                cep += ce; np++;
                float4 ld = loc4[(size_t)b * PP + p];
                float4 pr = priors4[p];
                float m0 = s_t[bti][0], m1 = s_t[bti][1];
                float m2 = s_t[bti][2], m3 = s_t[bti][3];
                float gx = ((m0 + m2) * 0.5f - pr.x) / (VAR0 * pr.z);
                float gy = ((m1 + m3) * 0.5f - pr.y) / (VAR0 * pr.w);
                float gw = __logf((m2 - m0) / pr.z) / VAR1;
                float gh = __logf((m3 - m1) / pr.w) / VAR1;
                ll += sl1(ld.x - gx) + sl1(ld.y - gy) +
                      sl1(ld.z - gw) + sl1(ld.w - gh);
            }
        }
        __syncwarp();
    }

    // block reduce (deterministic)
    ll = warp_red_f(ll); cep = warp_red_f(cep); np = warp_red_i(np);
    if (lane == 0) { s_rll[wid] = ll; s_rcep[wid] = cep; s_rnp[wid] = np; }
    __syncthreads();
    if (tid == 0) {
        float a = 0.0f, c = 0.0f; int nn = 0;
        for (int w = 0; w < NW; w++) { a += s_rll[w]; c += s_rcep[w]; nn += s_rnp[w]; }
        s_llT = a; s_cepT = c; s_npT = nn;
        sh_pref = 0u; sh_pmask = 0u;
        int k = NEGPOS * nn; if (k > PP - 1) k = PP - 1;
        sh_kk = k;
        s_negT = 0.0f;
    }
    __syncthreads();

    // ---- Phase 3: radix-select k-th largest of mined, sum neg CE ----
    const int k = sh_kk;
    if (k > 0) {
        for (int d = 3; d >= 0; d--) {
            for (int i = tid; i < 256; i += NT) s_hist[i] = 0u;
            __syncthreads();
            unsigned pref = sh_pref, pmask = sh_pmask;
            for (int p = tid; p < PP; p += NT) {
                unsigned u = g_mined[b * PP + p];
                if ((u & pmask) == pref)
                    atomicAdd(&s_hist[(u >> (d * 8)) & 255u], 1u);
            }
            __syncthreads();
            if (tid == 0) {
                int kk = sh_kk, cum = 0, dig = 0;
                for (int x = 255; x >= 0; x--) {
                    int c = (int)s_hist[x];
                    if (cum + c >= kk) { dig = x; break; }
                    cum += c;
                }
                sh_kk = kk - cum;
                sh_pref = sh_pref | ((unsigned)dig << (d * 8));
                sh_pmask = sh_pmask | (0xFFu << (d * 8));
            }
            __syncthreads();
        }
        unsigned vbits = sh_pref;
        float s = 0.0f;
        for (int p = tid; p < PP; p += NT) {
            unsigned u = g_mined[b * PP + p];
            if (u > vbits) s += __uint_as_float(u);
        }
        s = warp_red_f(s);
        if (lane == 0) s_rll[wid] = s;
        __syncthreads();
        if (tid == 0) {
            float tot = 0.0f;
            for (int w = 0; w < NW; w++) tot += s_rll[w];
            s_negT = tot + __uint_as_float(vbits) * (float)sh_kk;
        }
        __syncthreads();
    }

    if (tid == 0) {
        g_ll[b] = s_llT;
        g_lc[b] = s_cepT + s_negT;
        g_np[b] = s_npT;
    }
}

__global__ void mb_fin(float* __restrict__ out) {
    const int t = threadIdx.x;   // 128 threads
    const int lane = t & 31, wid = t >> 5;
    __shared__ float s_a[4], s_b[4];
    __shared__ int s_n[4];
    float ll = g_ll[t], lc = g_lc[t];
    int np = g_np[t];
    ll = warp_red_f(ll); lc = warp_red_f(lc); np = warp_red_i(np);
    if (lane == 0) { s_a[wid] = ll; s_b[wid] = lc; s_n[wid] = np; }
    __syncthreads();
    if (t == 0) {
        float llT = 0.0f, lcT = 0.0f; int npT = 0;
        for (int w = 0; w < 4; w++) { llT += s_a[w]; lcT += s_b[w]; npT += s_n[w]; }
        float N = (npT > 0) ? (float)npT : (float)BB;
        out[0] = llT / N;
        out[1] = lcT / N;
    }
}

extern "C" void kernel_launch(void* const* d_in, const int* in_sizes, int n_in,
                              void* d_out, int out_size) {
    const float4* loc4    = (const float4*)d_in[0];   // [B,P,4]
    const float*  conf    = (const float*)d_in[1];    // [B,P,21]
    const float4* priors4 = (const float4*)d_in[2];   // [P,4]
    const float*  targets = (const float*)d_in[3];    // [B,16,5]
    float* out = (float*)d_out;

    mb_main<<<BB, NT>>>(loc4, conf, priors4, targets);
    mb_fin<<<1, 128>>>(out);
}

// round 6
// speedup vs baseline: 1.5628x; 1.5628x over previous
#include <cuda_runtime.h>

#define BB 128
#define PP 34125
#define OO 16
#define CC 21
#define NEGPOS 3
#define VAR0 0.1f
#define VAR1 0.2f
#define THRESH 0.35f
#define NT 512
#define NW (NT/32)
#define NTILES ((PP + 31) / 32)

// scratch (device globals: allocation is forbidden)
__device__ unsigned short g_match[BB*PP];   // ct | (bti<<8)
__device__ unsigned       g_mined[BB*PP];   // CE bits (0 for positives)
__device__ float          g_ll[BB];
__device__ float          g_lc[BB];
__device__ int            g_np[BB];

__device__ __forceinline__ float warp_red_f(float v) {
    #pragma unroll
    for (int o = 16; o; o >>= 1) v += __shfl_down_sync(0xffffffffu, v, o);
    return v;
}
__device__ __forceinline__ int warp_red_i(int v) {
    #pragma unroll
    for (int o = 16; o; o >>= 1) v += __shfl_down_sync(0xffffffffu, v, o);
    return v;
}
__device__ __forceinline__ float sl1(float d) {
    float ad = fabsf(d);
    return (ad < 1.0f) ? 0.5f * d * d : ad - 0.5f;
}

// warp-0-collective: find crossing digit in 256-bin histogram (descending),
// update kk / pref / pmask for radix level d.
__device__ __forceinline__ void find_digit(const unsigned* s_hist, int lane, int d,
                                           int* p_kk, unsigned* p_pref, unsigned* p_pmask) {
    unsigned c8[8]; unsigned lsum = 0;
    #pragma unroll
    for (int j = 0; j < 8; j++) { c8[j] = s_hist[lane * 8 + j]; lsum += c8[j]; }
    unsigned sfx = lsum;                 // suffix sum over lanes >= lane
    #pragma unroll
    for (int off = 1; off < 32; off <<= 1) {
        unsigned w = __shfl_down_sync(0xffffffffu, sfx, off);
        if (lane + off < 32) sfx += w;
    }
    int kk = *p_kk;
    unsigned bal = __ballot_sync(0xffffffffu, sfx >= (unsigned)kk);
    int L = 31 - __clz(bal);             // highest lane whose suffix covers kk
    if (lane == L) {
        unsigned run = sfx - lsum;       // count strictly above this lane's bins
        int dig = 0;
        #pragma unroll
        for (int j = 7; j >= 0; j--) {
            if (run + c8[j] >= (unsigned)kk) { dig = L * 8 + j; break; }
            run += c8[j];
        }
        *p_kk = kk - (int)run;
        *p_pref |= (unsigned)dig << (d * 8);
        *p_pmask |= 0xFFu << (d * 8);
    }
}

__global__ __launch_bounds__(NT, 1) void mb_main(
    const float4* __restrict__ loc4,     // [B,P] float4
    const float*  __restrict__ conf,     // [B,P,C]
    const float4* __restrict__ priors4,  // [P] float4 (cx,cy,w,h)
    const float*  __restrict__ targets)  // [B,O,5]
{
    const int b = blockIdx.x;
    const int tid = threadIdx.x;
    const int lane = tid & 31;
    const int wid = tid >> 5;

    __shared__ float s_t[OO][5];
    __shared__ float s_area[OO];
    __shared__ unsigned long long s_bpk[OO];
    __shared__ float s_conf[NW][32 * CC];     // 43008 B
    __shared__ unsigned s_hist[256];
    __shared__ float s_rll[NW], s_rcep[NW];
    __shared__ int   s_rnp[NW];
    __shared__ float s_llT, s_cepT, s_negT;
    __shared__ int   s_npT;
    __shared__ unsigned sh_pref, sh_pmask;
    __shared__ int sh_kk;

    if (tid < OO * 5) s_t[tid / 5][tid % 5] = targets[b * OO * 5 + tid];
    if (tid < OO) s_bpk[tid] = 0ULL;
    if (tid < 256) s_hist[tid] = 0u;
    __syncthreads();
    if (tid < OO)
        s_area[tid] = (s_t[tid][2] - s_t[tid][0]) * (s_t[tid][3] - s_t[tid][1]);
    __syncthreads();

    // ---------------- Phase 1: matching ----------------
    float tx0[OO], ty0[OO], tx1[OO], ty1[OO];
    #pragma unroll
    for (int o = 0; o < OO; o++) {
        tx0[o] = s_t[o][0]; ty0[o] = s_t[o][1];
        tx1[o] = s_t[o][2]; ty1[o] = s_t[o][3];
    }
    float bIou[OO]; unsigned bP[OO];
    #pragma unroll
    for (int o = 0; o < OO; o++) { bIou[o] = -1.0f; bP[o] = 0u; }

    for (int p = tid; p < PP; p += NT) {
        float4 pr = priors4[p];
        float hw = pr.z * 0.5f, hh = pr.w * 0.5f;
        float px0 = pr.x - hw, py0 = pr.y - hh;
        float px1 = pr.x + hw, py1 = pr.y + hh;
        float pa = pr.z * pr.w;
        float bto = -1.0f; int bti = 0;
        #pragma unroll
        for (int o = 0; o < OO; o++) {
            float iw = fminf(tx1[o], px1) - fmaxf(tx0[o], px0);
            float ih = fminf(ty1[o], py1) - fmaxf(ty0[o], py0);
            iw = fmaxf(iw, 0.0f); ih = fmaxf(ih, 0.0f);
            float inter = iw * ih;
            float iou = __fdividef(inter, s_area[o] + pa - inter);
            if (iou > bto) { bto = iou; bti = o; }
            if (iou > bIou[o]) { bIou[o] = iou; bP[o] = (unsigned)p; } // first-p on ties
        }
        int ct = 0;
        if (bto >= THRESH) ct = (int)s_t[bti][4];
        g_match[(size_t)b * PP + p] = (unsigned short)(ct | (bti << 8));
    }
    // merge per-o best prior: warp shuffle reduce on packed key, then 1 atomic
    #pragma unroll
    for (int o = 0; o < OO; o++) {
        unsigned long long key =
            ((unsigned long long)__float_as_uint(bIou[o]) << 32) |
            (unsigned long long)(0xFFFFFFFFu - bP[o]);
        #pragma unroll
        for (int off = 16; off; off >>= 1) {
            unsigned long long w = __shfl_down_sync(0xffffffffu, key, off);
            if (w > key) key = w;
        }
        if (lane == 0) atomicMax(&s_bpk[o], key);
    }
    __syncthreads();
    if (tid == 0) {
        for (int o = 0; o < OO; o++) {   // sequential overrides, last-wins
            unsigned pstar = 0xFFFFFFFFu - (unsigned)(s_bpk[o] & 0xFFFFFFFFULL);
            g_match[(size_t)b * PP + pstar] =
                (unsigned short)(((int)s_t[o][4]) | (o << 8));
        }
    }
    __syncthreads();

    // ---------------- Phase 2: CE + loc loss (+ top-byte histogram) ----------------
    float ll = 0.0f, cep = 0.0f; int np = 0;
    for (int tile = wid; tile < NTILES; tile += NW) {
        int p32 = tile * 32;
        const float* cb = conf + ((size_t)b * PP + p32) * CC;
        float* sc = s_conf[wid];
        if (p32 + 32 <= PP) {
            #pragma unroll
            for (int i = 0; i < CC; i++) sc[i * 32 + lane] = cb[i * 32 + lane];
        } else {
            int lim = (PP - p32) * CC;
            #pragma unroll
            for (int i = 0; i < CC; i++) {
                int j = i * 32 + lane;
                sc[j] = cb[j < lim ? j : 0];
            }
        }
        __syncwarp();
        int n = min(32, PP - p32);
        bool actv = lane < n;
        unsigned u = 0u;
        if (actv) {
            int p = p32 + lane;
            const float* row = sc + lane * CC;   // stride 21: bank-conflict-free
            float s0 = 0.0f, s1 = 0.0f;
            #pragma unroll
            for (int c = 0; c < CC - 1; c += 2) {
                s0 += __expf(row[c]);
                s1 += __expf(row[c + 1]);
            }
            s0 += __expf(row[CC - 1]);
            float lse = __logf(s0 + s1);

            unsigned m = g_match[(size_t)b * PP + p];
            int ct = m & 0xFF, bti = m >> 8;
            float ce = lse - row[ct];
            bool pos = ct > 0;
            u = pos ? 0u : __float_as_uint(fmaxf(ce, 0.0f));
            g_mined[(size_t)b * PP + p] = u;
            if (pos) {
                cep += ce; np++;
                float4 ld = loc4[(size_t)b * PP + p];
                float4 pr = priors4[p];
                float m0 = s_t[bti][0], m1 = s_t[bti][1];
                float m2 = s_t[bti][2], m3 = s_t[bti][3];
                float gx = __fdividef((m0 + m2) * 0.5f - pr.x, VAR0 * pr.z);
                float gy = __fdividef((m1 + m3) * 0.5f - pr.y, VAR0 * pr.w);
                float gw = __logf(__fdividef(m2 - m0, pr.z)) * (1.0f / VAR1);
                float gh = __logf(__fdividef(m3 - m1, pr.w)) * (1.0f / VAR1);
                ll += sl1(ld.x - gx) + sl1(ld.y - gy) +
                      sl1(ld.z - gw) + sl1(ld.w - gh);
            }
        }
        // fold radix level d=3 histogram in (leader-aggregated counts)
        unsigned ab = __ballot_sync(0xffffffffu, actv);
        if (actv) {
            unsigned dig = u >> 24;
            unsigned peers = __match_any_sync(ab, dig);
            if ((peers & ((1u << lane) - 1)) == 0)
                atomicAdd(&s_hist[dig], (unsigned)__popc(peers));
        }
        __syncwarp();
    }

    ll = warp_red_f(ll); cep = warp_red_f(cep); np = warp_red_i(np);
    if (lane == 0) { s_rll[wid] = ll; s_rcep[wid] = cep; s_rnp[wid] = np; }
    __syncthreads();
    if (tid == 0) {
        float a = 0.0f, c = 0.0f; int nn = 0;
        for (int w = 0; w < NW; w++) { a += s_rll[w]; c += s_rcep[w]; nn += s_rnp[w]; }
        s_llT = a; s_cepT = c; s_npT = nn;
        int k = NEGPOS * nn; if (k > PP - 1) k = PP - 1;
        sh_kk = k; sh_pref = 0u; sh_pmask = 0u;
        s_negT = 0.0f;
    }
    __syncthreads();

    // ---------------- Phase 3: radix-select k-th largest + neg CE sum ----------------
    if (sh_kk > 0) {
        // level d=3 already histogrammed during phase 2
        if (wid == 0) find_digit(s_hist, lane, 3, &sh_kk, &sh_pref, &sh_pmask);
        __syncthreads();

        for (int d = 2; d >= 0; d--) {
            for (int i = tid; i < 256; i += NT) s_hist[i] = 0u;
            __syncthreads();
            unsigned pref = sh_pref, pmask = sh_pmask;
            for (int base = 0; base < PP; base += NT * 8) {
                unsigned uu[8]; bool vv[8];
                #pragma unroll
                for (int j = 0; j < 8; j++) {
                    int p = base + j * NT + tid;
                    unsigned x = (p < PP) ? g_mined[(size_t)b * PP + p] : 0u;
                    vv[j] = (p < PP) && ((x & pmask) == pref);
                    uu[j] = x;
                }
                #pragma unroll
                for (int j = 0; j < 8; j++) {
                    unsigned ab = __ballot_sync(0xffffffffu, vv[j]);
                    if (vv[j]) {
                        unsigned dig = (uu[j] >> (d * 8)) & 0xFFu;
                        unsigned peers = __match_any_sync(ab, dig);
                        if ((peers & ((1u << lane) - 1)) == 0)
                            atomicAdd(&s_hist[dig], (unsigned)__popc(peers));
                    }
                }
            }
            __syncthreads();
            if (wid == 0) find_digit(s_hist, lane, d, &sh_kk, &sh_pref, &sh_pmask);
            __syncthreads();
        }

        unsigned vb = sh_pref;           // k-th largest value (bits)
        float s = 0.0f;
        for (int base = 0; base < PP; base += NT * 8) {
            #pragma unroll
            for (int j = 0; j < 8; j++) {
                int p = base + j * NT + tid;
                if (p < PP) {
                    unsigned x = g_mined[(size_t)b * PP + p];
                    if (x > vb) s += __uint_as_float(x);
                }
            }
        }
        s = warp_red_f(s);
        if (lane == 0) s_rll[wid] = s;
        __syncthreads();
        if (tid == 0) {
            float tot = 0.0f;
            for (int w = 0; w < NW; w++) tot += s_rll[w];
            s_negT = tot + __uint_as_float(vb) * (float)sh_kk;
        }
        __syncthreads();
    }

    if (tid == 0) {
        g_ll[b] = s_llT;
        g_lc[b] = s_cepT + s_negT;
        g_np[b] = s_npT;
    }
}

__global__ void mb_fin(float* __restrict__ out) {
    const int t = threadIdx.x;   // 128 threads
    const int lane = t & 31, wid = t >> 5;
    __shared__ float s_a[4], s_b[4];
    __shared__ int s_n[4];
    float ll = g_ll[t], lc = g_lc[t];
    int np = g_np[t];
    ll = warp_red_f(ll); lc = warp_red_f(lc); np = warp_red_i(np);
    if (lane == 0) { s_a[wid] = ll; s_b[wid] = lc; s_n[wid] = np; }
    __syncthreads();
    if (t == 0) {
        float llT = 0.0f, lcT = 0.0f; int npT = 0;
        for (int w = 0; w < 4; w++) { llT += s_a[w]; lcT += s_b[w]; npT += s_n[w]; }
        float N = (npT > 0) ? (float)npT : (float)BB;
        out[0] = llT / N;
        out[1] = lcT / N;
    }
}

extern "C" void kernel_launch(void* const* d_in, const int* in_sizes, int n_in,
                              void* d_out, int out_size) {
    const float4* loc4    = (const float4*)d_in[0];   // [B,P,4]
    const float*  conf    = (const float*)d_in[1];    // [B,P,21]
    const float4* priors4 = (const float4*)d_in[2];   // [P,4]
    const float*  targets = (const float*)d_in[3];    // [B,16,5]
    float* out = (float*)d_out;

    mb_main<<<BB, NT>>>(loc4, conf, priors4, targets);
    mb_fin<<<1, 128>>>(out);
}